// round 4
// baseline (speedup 1.0000x reference)
#include <cuda_runtime.h>
#include <cuda_bf16.h>
#include <cstdint>

// LeftPool: out[b,c,h,w] = max(x[b,c,h,w:]) — reverse cummax along width (=128, contiguous).
// One warp per row: lane i owns elements [4i, 4i+4). Perfectly coalesced float4 IO.
//
// Steps per warp:
//  1. float4 load (512 B/warp, contiguous)
//  2. in-lane suffix max over the 4 elements
//  3. warp suffix-scan of lane maxima (5x shfl_down + fmax), shifted to exclusive
//  4. fold exclusive suffix into all 4 elements, float4 store

__global__ void __launch_bounds__(256) leftpool_kernel(
    const float4* __restrict__ x, float4* __restrict__ out, int nrows)
{
    const int gwarp = (int)((blockIdx.x * blockDim.x + threadIdx.x) >> 5);
    const int lane  = threadIdx.x & 31;
    if (gwarp >= nrows) return;

    const size_t base = (size_t)gwarp * 32 + lane;   // float4 index
    float4 v = x[base];

    // In-lane suffix max: after this, v.k = max(orig v.k .. v.w)
    v.z = fmaxf(v.z, v.w);
    v.y = fmaxf(v.y, v.z);
    v.x = fmaxf(v.x, v.y);

    // Inclusive suffix max across lanes of the per-lane max (v.x)
    float m = v.x;
    #pragma unroll
    for (int d = 1; d < 32; d <<= 1) {
        float t = __shfl_down_sync(0xffffffffu, m, d);
        m = fmaxf(m, t);   // out-of-range shfl returns own value -> harmless
    }
    // Exclusive suffix (max over lanes strictly greater): shift down by one.
    float s = __shfl_down_sync(0xffffffffu, m, 1);
    if (lane == 31) s = __int_as_float(0xff800000u);  // -inf

    v.x = fmaxf(v.x, s);
    v.y = fmaxf(v.y, s);
    v.z = fmaxf(v.z, s);
    v.w = fmaxf(v.w, s);

    out[base] = v;
}

extern "C" void kernel_launch(void* const* d_in, const int* in_sizes, int n_in,
                              void* d_out, int out_size)
{
    const float* x = (const float*)d_in[0];
    float* out = (float*)d_out;

    const int W = 128;                       // width axis (contiguous, per reference)
    const int nrows = in_sizes[0] / W;       // 16*256*128 = 524288 rows

    const int threads = 256;                 // 8 warps per block -> 8 rows per block
    const int warps_per_block = threads / 32;
    const int blocks = (nrows + warps_per_block - 1) / warps_per_block;

    leftpool_kernel<<<blocks, threads>>>(
        (const float4*)x, (float4*)out, nrows);
}

// round 5
// speedup vs baseline: 1.0500x; 1.0500x over previous
#include <cuda_runtime.h>
#include <cuda_bf16.h>
#include <cstdint>

// LeftPool: out[b,c,h,w] = max(x[b,c,h,w:]) — reverse cummax along width (=128, contiguous).
//
// One warp per TWO rows (row g and row g + nrows/2), lane i owns float4 i of each row.
// Both loads issued up front (MLP=2/thread), two independent suffix-scan chains
// interleave so SHFL latency (26 cyc) is hidden by the sibling chain.
// All loads/stores remain perfectly coalesced 128B-line accesses.

__global__ void __launch_bounds__(256) leftpool_kernel(
    const float4* __restrict__ x, float4* __restrict__ out, int half)
{
    const int gwarp = (int)((blockIdx.x * blockDim.x + threadIdx.x) >> 5);
    const int lane  = threadIdx.x & 31;
    if (gwarp >= half) return;

    const size_t b0 = (size_t)gwarp * 32 + lane;          // float4 index, row g
    const size_t b1 = b0 + (size_t)half * 32;             // row g + half

    // Issue both loads before any dependent work.
    float4 v0 = x[b0];
    float4 v1 = x[b1];

    // In-lane suffix max (independent chains interleave).
    v0.z = fmaxf(v0.z, v0.w);  v1.z = fmaxf(v1.z, v1.w);
    v0.y = fmaxf(v0.y, v0.z);  v1.y = fmaxf(v1.y, v1.z);
    v0.x = fmaxf(v0.x, v0.y);  v1.x = fmaxf(v1.x, v1.y);

    // Inclusive suffix max across lanes of per-lane maxima; two chains in parallel.
    float m0 = v0.x, m1 = v1.x;
    #pragma unroll
    for (int d = 1; d < 32; d <<= 1) {
        float t0 = __shfl_down_sync(0xffffffffu, m0, d);
        float t1 = __shfl_down_sync(0xffffffffu, m1, d);
        m0 = fmaxf(m0, t0);        // out-of-range shfl returns own value -> harmless
        m1 = fmaxf(m1, t1);
    }
    // Exclusive suffix: shift down by one; lane 31 sees -inf.
    float s0 = __shfl_down_sync(0xffffffffu, m0, 1);
    float s1 = __shfl_down_sync(0xffffffffu, m1, 1);
    if (lane == 31) {
        s0 = __int_as_float(0xff800000u);
        s1 = __int_as_float(0xff800000u);
    }

    v0.x = fmaxf(v0.x, s0);  v1.x = fmaxf(v1.x, s1);
    v0.y = fmaxf(v0.y, s0);  v1.y = fmaxf(v1.y, s1);
    v0.z = fmaxf(v0.z, s0);  v1.z = fmaxf(v1.z, s1);
    v0.w = fmaxf(v0.w, s0);  v1.w = fmaxf(v1.w, s1);

    out[b0] = v0;
    out[b1] = v1;
}

extern "C" void kernel_launch(void* const* d_in, const int* in_sizes, int n_in,
                              void* d_out, int out_size)
{
    const float* x = (const float*)d_in[0];
    float* out = (float*)d_out;

    const int W = 128;                         // contiguous width axis
    const int nrows = in_sizes[0] / W;         // 524288
    const int half = nrows / 2;                // 262144 warps, 2 rows each

    const int threads = 256;                   // 8 warps/block
    const int warps_per_block = threads / 32;
    const int blocks = (half + warps_per_block - 1) / warps_per_block;  // 32768

    leftpool_kernel<<<blocks, threads>>>(
        (const float4*)x, (float4*)out, half);
}